// round 5
// baseline (speedup 1.0000x reference)
#include <cuda_runtime.h>
#include <cuda_fp16.h>
#include <cstdint>
#include <cstddef>

// ============================================================================
// MultiHeadAttention on GB300 — FP16 mma.sync, CTA 128x256, warp 64x64
//   conv : x, W -> fp16
//   GEMM1: Yh[16384,3072] = Xh @ Wqkv^T
//   attn : per-token 16x16 head attention (fp32 math, fp16 V in smem)
//   GEMM2: out(fp32) = Oh @ Wfc^T
// ============================================================================

#define NSTG 3
#define STAGE_B 24576          // A 8KB + B 16KB
#define CTA_M 128
#define CTA_N 256
#define SMEM_TOTAL (NSTG * STAGE_B)   // 73728

__device__ __half g_Yh[50331648];   // 16384 x 3072
__device__ __half g_Oh[16777216];   // 16384 x 1024
__device__ __half g_Xh[16777216];   // x in fp16
__device__ __half g_Wh[4194304];    // Wq|Wk|Wv|Wfc in fp16

// ---------------------------------------------------------------- helpers
__device__ __forceinline__ uint32_t smem_u32(const void* p) {
    uint32_t a;
    asm("{ .reg .u64 t; cvta.to.shared.u64 t, %1; cvt.u32.u64 %0, t; }"
        : "=r"(a) : "l"(p));
    return a;
}
__device__ __forceinline__ void cp16(uint32_t saddr, const void* gptr) {
    asm volatile("cp.async.cg.shared.global [%0], [%1], 16;\n" :: "r"(saddr), "l"(gptr));
}
__device__ __forceinline__ void cp_commit() { asm volatile("cp.async.commit_group;\n"); }
template <int N>
__device__ __forceinline__ void cp_wait() {
    asm volatile("cp.async.wait_group %0;\n" :: "n"(N));
}
__device__ __forceinline__ void ldsm4(uint32_t& r0, uint32_t& r1, uint32_t& r2,
                                      uint32_t& r3, uint32_t addr) {
    asm volatile("ldmatrix.sync.aligned.m8n8.x4.shared.b16 {%0,%1,%2,%3}, [%4];"
                 : "=r"(r0), "=r"(r1), "=r"(r2), "=r"(r3) : "r"(addr));
}
__device__ __forceinline__ void mma_f16(float c[4], const uint32_t a[4], const uint32_t b[2]) {
    asm volatile(
        "mma.sync.aligned.m16n8k16.row.col.f32.f16.f16.f32 "
        "{%0,%1,%2,%3}, {%4,%5,%6,%7}, {%8,%9}, {%0,%1,%2,%3};\n"
        : "+f"(c[0]), "+f"(c[1]), "+f"(c[2]), "+f"(c[3])
        : "r"(a[0]), "r"(a[1]), "r"(a[2]), "r"(a[3]), "r"(b[0]), "r"(b[1]));
}

// ============================================================================
// FP16 NT GEMM: C[128x256 tile] = A[M,K] @ B[N,K]^T
// 8 warps, warp tile 64x64. smem row = 64B, swizzle g' = g ^ ((row>>1)&3)
// ============================================================================
template <bool OUT_HALF>
__global__ void __launch_bounds__(256, 1)
gemm_f16_nt(const __half* __restrict__ A, const __half* __restrict__ B,
            void* __restrict__ Cout, int ldc, int K)
{
    extern __shared__ __align__(128) char smem[];
    const uint32_t sb = smem_u32(smem);

    const int tid  = threadIdx.x;
    const int lane = tid & 31;
    const int wid  = tid >> 5;
    const int warp_m = wid & 1;     // 64 rows
    const int warp_n = wid >> 1;    // 64 cols

    const int mtile = blockIdx.y, ntile = blockIdx.x;
    const __half* Ab = A + (size_t)(mtile * CTA_M) * K;
    const __half* Bb = B + (size_t)(ntile * CTA_N) * K;

    // -------- loader: 6x cp16 per thread per k-tile (A 512 + B 1024 float4s)
    const __half* gsrc[6];
    uint32_t soff[6];
#pragma unroll
    for (int i = 0; i < 6; i++) {
        const int id = tid + i * 256;       // 0..1535
        if (id < 512) {                     // A
            const int rr = id >> 2, g = id & 3;
            gsrc[i] = Ab + (size_t)rr * K + g * 8;
            soff[i] = (uint32_t)(rr * 64 + ((g ^ ((rr >> 1) & 3)) << 4));
        } else {                            // B
            const int idb = id - 512;
            const int rr = idb >> 2, g = idb & 3;
            gsrc[i] = Bb + (size_t)rr * K + g * 8;
            soff[i] = (uint32_t)(8192 + rr * 64 + ((g ^ ((rr >> 1) & 3)) << 4));
        }
    }

    // -------- ldmatrix fragment base addresses (stage 0, ks=0)
    const int ch = lane >> 4;
    uint32_t a_addr[4], b_addr[4];
#pragma unroll
    for (int mt = 0; mt < 4; mt++) {
        const int r = warp_m * 64 + mt * 16 + (lane & 15);
        a_addr[mt] = sb + r * 64 + ((ch ^ ((r >> 1) & 3)) << 4);
    }
#pragma unroll
    for (int p = 0; p < 4; p++) {
        const int r = warp_n * 64 + p * 16 + (lane & 15);
        b_addr[p] = sb + 8192 + r * 64 + ((ch ^ ((r >> 1) & 3)) << 4);
    }

    float acc[4][8][4];
#pragma unroll
    for (int mt = 0; mt < 4; mt++)
#pragma unroll
        for (int nt = 0; nt < 8; nt++)
#pragma unroll
            for (int i = 0; i < 4; i++) acc[mt][nt][i] = 0.f;

    const int NKT = K >> 5;

    // prefill NSTG-1 stages
#pragma unroll
    for (int s = 0; s < NSTG - 1; s++) {
#pragma unroll
        for (int i = 0; i < 6; i++) cp16(sb + s * STAGE_B + soff[i], gsrc[i] + s * 32);
        cp_commit();
    }

    for (int kt = 0; kt < NKT; kt++) {
        cp_wait<NSTG - 2>();
        __syncthreads();

        const int nk = kt + NSTG - 1;
        if (nk < NKT) {
            const uint32_t so = (uint32_t)(nk % NSTG) * STAGE_B;
#pragma unroll
            for (int i = 0; i < 6; i++) cp16(sb + so + soff[i], gsrc[i] + nk * 32);
            cp_commit();
        } else {
            cp_commit();
        }

        const uint32_t so = (uint32_t)(kt % NSTG) * STAGE_B;

#pragma unroll
        for (int ks = 0; ks < 2; ks++) {
            const uint32_t kx = (uint32_t)ks << 5;
            uint32_t a[4][4], b[8][2];
#pragma unroll
            for (int mt = 0; mt < 4; mt++)
                ldsm4(a[mt][0], a[mt][1], a[mt][2], a[mt][3],
                      (a_addr[mt] + so) ^ kx);
#pragma unroll
            for (int p = 0; p < 4; p++) {
                uint32_t t0, t1, t2, t3;
                ldsm4(t0, t1, t2, t3, (b_addr[p] + so) ^ kx);
                b[2 * p][0] = t0; b[2 * p][1] = t2;
                b[2 * p + 1][0] = t1; b[2 * p + 1][1] = t3;
            }
#pragma unroll
            for (int mt = 0; mt < 4; mt++)
#pragma unroll
                for (int nt = 0; nt < 8; nt++)
                    mma_f16(acc[mt][nt], a[mt], b[nt]);
        }
    }

    // -------- epilogue
    const int r_in = lane >> 2;
    const int c_in = 2 * (lane & 3);
    if (OUT_HALF) {
        __half* Cb = (__half*)Cout + (size_t)(mtile * CTA_M) * ldc
                   + (size_t)ntile * CTA_N;
#pragma unroll
        for (int mt = 0; mt < 4; mt++)
#pragma unroll
            for (int nt = 0; nt < 8; nt++) {
                const int r0 = warp_m * 64 + mt * 16 + r_in;
                const int c0 = warp_n * 64 + nt * 8 + c_in;
                *(__half2*)(Cb + (size_t)r0 * ldc + c0) =
                    __floats2half2_rn(acc[mt][nt][0], acc[mt][nt][1]);
                *(__half2*)(Cb + (size_t)(r0 + 8) * ldc + c0) =
                    __floats2half2_rn(acc[mt][nt][2], acc[mt][nt][3]);
            }
    } else {
        float* Cb = (float*)Cout + (size_t)(mtile * CTA_M) * ldc
                  + (size_t)ntile * CTA_N;
#pragma unroll
        for (int mt = 0; mt < 4; mt++)
#pragma unroll
            for (int nt = 0; nt < 8; nt++) {
                const int r0 = warp_m * 64 + mt * 16 + r_in;
                const int c0 = warp_n * 64 + nt * 8 + c_in;
                *(float2*)(Cb + (size_t)r0 * ldc + c0) =
                    make_float2(acc[mt][nt][0], acc[mt][nt][1]);
                *(float2*)(Cb + (size_t)(r0 + 8) * ldc + c0) =
                    make_float2(acc[mt][nt][2], acc[mt][nt][3]);
            }
    }
}

// ============================================================================
// fp32 -> fp16 converters
// ============================================================================
__global__ void __launch_bounds__(256)
f2h_x(const float4* __restrict__ src, uint2* __restrict__ dst, int n4)
{
    int i = blockIdx.x * 256 + threadIdx.x;
    if (i < n4) {
        float4 v = src[i];
        __half2 h0 = __floats2half2_rn(v.x, v.y);
        __half2 h1 = __floats2half2_rn(v.z, v.w);
        uint2 o;
        o.x = *(uint32_t*)&h0;
        o.y = *(uint32_t*)&h1;
        dst[i] = o;
    }
}

__global__ void __launch_bounds__(256)
f2h_w(const float4* __restrict__ w0, const float4* __restrict__ w1,
      const float4* __restrict__ w2, const float4* __restrict__ w3,
      uint2* __restrict__ dst)
{
    int bx = blockIdx.x;
    int m  = bx >> 10;
    int i  = (bx & 1023) * 256 + threadIdx.x;
    const float4* src = (m == 0) ? w0 : (m == 1) ? w1 : (m == 2) ? w2 : w3;
    float4 v = src[i];
    __half2 h0 = __floats2half2_rn(v.x, v.y);
    __half2 h1 = __floats2half2_rn(v.z, v.w);
    uint2 o;
    o.x = *(uint32_t*)&h0;
    o.y = *(uint32_t*)&h1;
    dst[(size_t)m * 262144 + i] = o;
}

// ============================================================================
// Per-token head-axis attention: one warp/token, 2 tokens/block.
// Q,K staged fp32; V kept half2 in smem (conflict-free AV loads).
// ============================================================================
#define QK_LD 68
#define V_LD2 36    // half2 stride per V row (32 data + 4 pad; 16B-aligned rows)
#define TOK_FLOATS (2 * 16 * QK_LD + 16 * 17 + 16 * V_LD2)   // 3024
__global__ void __launch_bounds__(64)
attn_kernel(const __half* __restrict__ Y, __half* __restrict__ O)
{
    __shared__ __align__(16) float sm[2][TOK_FLOATS];

    const int lane = threadIdx.x & 31;
    const int w    = threadIdx.x >> 5;
    const int m    = blockIdx.x * 2 + w;

    float* q  = &sm[w][0];
    float* k  = q + 16 * QK_LD;
    float* sc = k + 16 * QK_LD;
    uint32_t* v32 = (uint32_t*)(sc + 16 * 17);

    const uint4* src = (const uint4*)(Y + (size_t)m * 3072);   // 384 uint4

#pragma unroll
    for (int it = 0; it < 12; it++) {
        const int f = it * 32 + lane;              // 0..383
        uint4 raw = src[f];
        if (f < 256) {                             // Q, K -> fp32
            const int sec  = f >> 7;
            const int wi   = f & 127;
            const int row  = wi >> 3;
            const int col8 = wi & 7;
            float* dst = sec ? k : q;
            const __half2* hp = (const __half2*)&raw;
            float2 f0 = __half22float2(hp[0]);
            float2 f1 = __half22float2(hp[1]);
            float2 f2 = __half22float2(hp[2]);
            float2 f3 = __half22float2(hp[3]);
            float* d = dst + row * QK_LD + col8 * 8;
            *(float4*)(d)     = make_float4(f0.x, f0.y, f1.x, f1.y);
            *(float4*)(d + 4) = make_float4(f2.x, f2.y, f3.x, f3.y);
        } else {                                   // V stays fp16
            const int wi   = f & 127;
            const int row  = wi >> 3;
            const int col8 = wi & 7;
            *(uint4*)(v32 + row * V_LD2 + col8 * 4) = raw;
        }
    }
    __syncwarp();

    // scores[h][t] = Q[h]·K[t] / 8
#pragma unroll
    for (int p = 0; p < 8; p++) {
        const int idx = p * 32 + lane;
        const int h = idx >> 4, t = idx & 15;
        float s = 0.f;
#pragma unroll
        for (int d4 = 0; d4 < 16; d4++) {
            float4 qv = *(const float4*)(q + h * QK_LD + d4 * 4);
            float4 kv = *(const float4*)(k + t * QK_LD + d4 * 4);
            s += qv.x * kv.x + qv.y * kv.y + qv.z * kv.z + qv.w * kv.w;
        }
        sc[h * 17 + t] = s * 0.125f;
    }
    __syncwarp();

    if (lane < 16) {
        float mx = -1e30f;
#pragma unroll
        for (int t = 0; t < 16; t++) mx = fmaxf(mx, sc[lane * 17 + t]);
        float sum = 0.f;
#pragma unroll
        for (int t = 0; t < 16; t++) {
            float e = __expf(sc[lane * 17 + t] - mx);
            sum += e;
            sc[lane * 17 + t] = e;
        }
        const float inv = 1.f / sum;
#pragma unroll
        for (int t = 0; t < 16; t++) sc[lane * 17 + t] *= inv;
    }
    __syncwarp();

    // O[h][2*lane..2*lane+1] = sum_t attn[h][t] * V[t][..]
    const __half2* vh = (const __half2*)v32;
    __half* dst = O + (size_t)m * 1024;
#pragma unroll
    for (int h = 0; h < 16; h++) {
        float a0 = 0.f, a1 = 0.f;
#pragma unroll
        for (int t = 0; t < 16; t++) {
            const float s = sc[h * 17 + t];
            float2 vv = __half22float2(vh[t * V_LD2 + lane]);
            a0 += s * vv.x;
            a1 += s * vv.y;
        }
        *(__half2*)(dst + h * 64 + 2 * lane) = __floats2half2_rn(a0, a1);
    }
}

// ============================================================================
extern "C" void kernel_launch(void* const* d_in, const int* in_sizes, int n_in,
                              void* d_out, int out_size)
{
    (void)in_sizes; (void)n_in; (void)out_size;
    const float* x   = (const float*)d_in[0];
    const float* Wq  = (const float*)d_in[1];
    const float* Wk  = (const float*)d_in[2];
    const float* Wv  = (const float*)d_in[3];
    const float* Wfc = (const float*)d_in[4];
    float* out = (float*)d_out;

    __half *Yh, *Oh, *Xh, *Wh;
    cudaGetSymbolAddress((void**)&Yh, g_Yh);
    cudaGetSymbolAddress((void**)&Oh, g_Oh);
    cudaGetSymbolAddress((void**)&Xh, g_Xh);
    cudaGetSymbolAddress((void**)&Wh, g_Wh);

    cudaFuncSetAttribute(gemm_f16_nt<true>,
                         cudaFuncAttributeMaxDynamicSharedMemorySize, SMEM_TOTAL);
    cudaFuncSetAttribute(gemm_f16_nt<false>,
                         cudaFuncAttributeMaxDynamicSharedMemorySize, SMEM_TOTAL);

    // fp16 conversion
    f2h_x<<<16384, 256>>>((const float4*)x, (uint2*)Xh, 4194304);
    f2h_w<<<4096, 256>>>((const float4*)Wq, (const float4*)Wk,
                         (const float4*)Wv, (const float4*)Wfc, (uint2*)Wh);

    // GEMM1: Yh = Xh @ [Wq;Wk;Wv]^T   (tiles: 12 x 128)
    gemm_f16_nt<true><<<dim3(12, 128), 256, SMEM_TOTAL>>>(Xh, Wh, Yh, 3072, 1024);
    // attention
    attn_kernel<<<8192, 64>>>(Yh, Oh);
    // GEMM2: out = Oh @ Wfc^T         (tiles: 4 x 128)
    gemm_f16_nt<false><<<dim3(4, 128), 256, SMEM_TOTAL>>>(Oh, Wh + 3145728, out, 1024, 1024);
}

// round 6
// speedup vs baseline: 1.1569x; 1.1569x over previous
#include <cuda_runtime.h>
#include <cuda_fp16.h>
#include <cstdint>
#include <cstddef>

// ============================================================================
// MultiHeadAttention on GB300 — FP16 mma.sync, CTA 128x128, warp 64x32,
// 2 CTA/SM, 4-stage cp.async pipeline.
//   conv : x, W -> fp16
//   GEMM1: Yh[16384,3072] = Xh @ Wqkv^T
//   attn : per-token 16x16 head attention (fp32 QK, fp16 V in smem)
//   GEMM2: out(fp32) = Oh @ Wfc^T
// ============================================================================

#define NSTG 4
#define STAGE_B 16384          // A 8KB + B 8KB
#define CTA_M 128
#define CTA_N 128
#define SMEM_TOTAL (NSTG * STAGE_B)   // 65536

__device__ __half g_Yh[50331648];   // 16384 x 3072
__device__ __half g_Oh[16777216];   // 16384 x 1024
__device__ __half g_Xh[16777216];   // x in fp16
__device__ __half g_Wh[4194304];    // Wq|Wk|Wv|Wfc in fp16

// ---------------------------------------------------------------- helpers
__device__ __forceinline__ uint32_t smem_u32(const void* p) {
    uint32_t a;
    asm("{ .reg .u64 t; cvta.to.shared.u64 t, %1; cvt.u32.u64 %0, t; }"
        : "=r"(a) : "l"(p));
    return a;
}
__device__ __forceinline__ void cp16(uint32_t saddr, const void* gptr) {
    asm volatile("cp.async.cg.shared.global [%0], [%1], 16;\n" :: "r"(saddr), "l"(gptr));
}
__device__ __forceinline__ void cp_commit() { asm volatile("cp.async.commit_group;\n"); }
template <int N>
__device__ __forceinline__ void cp_wait() {
    asm volatile("cp.async.wait_group %0;\n" :: "n"(N));
}
__device__ __forceinline__ void ldsm4(uint32_t& r0, uint32_t& r1, uint32_t& r2,
                                      uint32_t& r3, uint32_t addr) {
    asm volatile("ldmatrix.sync.aligned.m8n8.x4.shared.b16 {%0,%1,%2,%3}, [%4];"
                 : "=r"(r0), "=r"(r1), "=r"(r2), "=r"(r3) : "r"(addr));
}
__device__ __forceinline__ void mma_f16(float c[4], const uint32_t a[4], const uint32_t b[2]) {
    asm volatile(
        "mma.sync.aligned.m16n8k16.row.col.f32.f16.f16.f32 "
        "{%0,%1,%2,%3}, {%4,%5,%6,%7}, {%8,%9}, {%0,%1,%2,%3};\n"
        : "+f"(c[0]), "+f"(c[1]), "+f"(c[2]), "+f"(c[3])
        : "r"(a[0]), "r"(a[1]), "r"(a[2]), "r"(a[3]), "r"(b[0]), "r"(b[1]));
}

// ============================================================================
// FP16 NT GEMM: C[128x128 tile] = A[M,K] @ B[N,K]^T
// 8 warps, warp tile 64x32. smem row = 64B, swizzle g' = g ^ ((row>>1)&3)
// ============================================================================
template <bool OUT_HALF>
__global__ void __launch_bounds__(256, 2)
gemm_f16_nt(const __half* __restrict__ A, const __half* __restrict__ B,
            void* __restrict__ Cout, int ldc, int K)
{
    extern __shared__ __align__(128) char smem[];
    const uint32_t sb = smem_u32(smem);

    const int tid  = threadIdx.x;
    const int lane = tid & 31;
    const int wid  = tid >> 5;
    const int warp_m = wid & 1;     // 64 rows
    const int warp_n = wid >> 1;    // 32 cols

    const int mtile = blockIdx.y, ntile = blockIdx.x;
    const __half* Ab = A + (size_t)(mtile * CTA_M) * K;
    const __half* Bb = B + (size_t)(ntile * CTA_N) * K;

    // -------- loader: 4x cp16 per thread per k-tile
    const __half* gsrc[4];
    uint32_t soff[4];
#pragma unroll
    for (int i = 0; i < 4; i++) {
        const int id = tid + i * 256;       // 0..1023
        const int op = id >> 9;             // 0=A 1=B
        const int rr = (id >> 2) & 127;
        const int g  = id & 3;
        gsrc[i] = (op ? Bb : Ab) + (size_t)rr * K + g * 8;
        soff[i] = (uint32_t)(op * 8192 + rr * 64 + ((g ^ ((rr >> 1) & 3)) << 4));
    }

    // -------- ldmatrix fragment base addresses (stage 0, ks=0)
    const int ch = lane >> 4;
    uint32_t a_addr[4], b_addr[2];
#pragma unroll
    for (int mt = 0; mt < 4; mt++) {
        const int r = warp_m * 64 + mt * 16 + (lane & 15);
        a_addr[mt] = sb + r * 64 + ((ch ^ ((r >> 1) & 3)) << 4);
    }
#pragma unroll
    for (int p = 0; p < 2; p++) {
        const int r = warp_n * 32 + p * 16 + (lane & 15);
        b_addr[p] = sb + 8192 + r * 64 + ((ch ^ ((r >> 1) & 3)) << 4);
    }

    float acc[4][4][4];
#pragma unroll
    for (int mt = 0; mt < 4; mt++)
#pragma unroll
        for (int nt = 0; nt < 4; nt++)
#pragma unroll
            for (int i = 0; i < 4; i++) acc[mt][nt][i] = 0.f;

    const int NKT = K >> 5;

    // prefill NSTG-1 stages
#pragma unroll
    for (int s = 0; s < NSTG - 1; s++) {
#pragma unroll
        for (int i = 0; i < 4; i++) cp16(sb + s * STAGE_B + soff[i], gsrc[i] + s * 32);
        cp_commit();
    }

    for (int kt = 0; kt < NKT; kt++) {
        cp_wait<NSTG - 2>();
        __syncthreads();

        const int nk = kt + NSTG - 1;
        if (nk < NKT) {
            const uint32_t so = (uint32_t)(nk % NSTG) * STAGE_B;
#pragma unroll
            for (int i = 0; i < 4; i++) cp16(sb + so + soff[i], gsrc[i] + nk * 32);
            cp_commit();
        } else {
            cp_commit();    // keep group count aligned with waits
        }

        const uint32_t so = (uint32_t)(kt % NSTG) * STAGE_B;

#pragma unroll
        for (int ks = 0; ks < 2; ks++) {
            const uint32_t kx = (uint32_t)ks << 5;
            uint32_t a[4][4], b[4][2];
#pragma unroll
            for (int mt = 0; mt < 4; mt++)
                ldsm4(a[mt][0], a[mt][1], a[mt][2], a[mt][3],
                      (a_addr[mt] + so) ^ kx);
#pragma unroll
            for (int p = 0; p < 2; p++) {
                uint32_t t0, t1, t2, t3;
                ldsm4(t0, t1, t2, t3, (b_addr[p] + so) ^ kx);
                b[2 * p][0] = t0; b[2 * p][1] = t2;
                b[2 * p + 1][0] = t1; b[2 * p + 1][1] = t3;
            }
#pragma unroll
            for (int mt = 0; mt < 4; mt++)
#pragma unroll
                for (int nt = 0; nt < 4; nt++)
                    mma_f16(acc[mt][nt], a[mt], b[nt]);
        }
    }

    // -------- epilogue
    const int r_in = lane >> 2;
    const int c_in = 2 * (lane & 3);
    if (OUT_HALF) {
        __half* Cb = (__half*)Cout + (size_t)(mtile * CTA_M) * ldc
                   + (size_t)ntile * CTA_N;
#pragma unroll
        for (int mt = 0; mt < 4; mt++)
#pragma unroll
            for (int nt = 0; nt < 4; nt++) {
                const int r0 = warp_m * 64 + mt * 16 + r_in;
                const int c0 = warp_n * 32 + nt * 8 + c_in;
                *(__half2*)(Cb + (size_t)r0 * ldc + c0) =
                    __floats2half2_rn(acc[mt][nt][0], acc[mt][nt][1]);
                *(__half2*)(Cb + (size_t)(r0 + 8) * ldc + c0) =
                    __floats2half2_rn(acc[mt][nt][2], acc[mt][nt][3]);
            }
    } else {
        float* Cb = (float*)Cout + (size_t)(mtile * CTA_M) * ldc
                  + (size_t)ntile * CTA_N;
#pragma unroll
        for (int mt = 0; mt < 4; mt++)
#pragma unroll
            for (int nt = 0; nt < 4; nt++) {
                const int r0 = warp_m * 64 + mt * 16 + r_in;
                const int c0 = warp_n * 32 + nt * 8 + c_in;
                *(float2*)(Cb + (size_t)r0 * ldc + c0) =
                    make_float2(acc[mt][nt][0], acc[mt][nt][1]);
                *(float2*)(Cb + (size_t)(r0 + 8) * ldc + c0) =
                    make_float2(acc[mt][nt][2], acc[mt][nt][3]);
            }
    }
}

// ============================================================================
// fp32 -> fp16 converters
// ============================================================================
__global__ void __launch_bounds__(256)
f2h_x(const float4* __restrict__ src, uint2* __restrict__ dst, int n4)
{
    int i = blockIdx.x * 256 + threadIdx.x;
    if (i < n4) {
        float4 v = src[i];
        __half2 h0 = __floats2half2_rn(v.x, v.y);
        __half2 h1 = __floats2half2_rn(v.z, v.w);
        uint2 o;
        o.x = *(uint32_t*)&h0;
        o.y = *(uint32_t*)&h1;
        dst[i] = o;
    }
}

__global__ void __launch_bounds__(256)
f2h_w(const float4* __restrict__ w0, const float4* __restrict__ w1,
      const float4* __restrict__ w2, const float4* __restrict__ w3,
      uint2* __restrict__ dst)
{
    int bx = blockIdx.x;
    int m  = bx >> 10;
    int i  = (bx & 1023) * 256 + threadIdx.x;
    const float4* src = (m == 0) ? w0 : (m == 1) ? w1 : (m == 2) ? w2 : w3;
    float4 v = src[i];
    __half2 h0 = __floats2half2_rn(v.x, v.y);
    __half2 h1 = __floats2half2_rn(v.z, v.w);
    uint2 o;
    o.x = *(uint32_t*)&h0;
    o.y = *(uint32_t*)&h1;
    dst[(size_t)m * 262144 + i] = o;
}

// ============================================================================
// Per-token head-axis attention: one warp/token, 2 tokens/block.
// Q,K staged fp32; V kept half2 in smem (conflict-free AV loads).
// ============================================================================
#define QK_LD 68
#define V_LD2 36
#define TOK_FLOATS (2 * 16 * QK_LD + 16 * 17 + 16 * V_LD2)
__global__ void __launch_bounds__(64)
attn_kernel(const __half* __restrict__ Y, __half* __restrict__ O)
{
    __shared__ __align__(16) float sm[2][TOK_FLOATS];

    const int lane = threadIdx.x & 31;
    const int w    = threadIdx.x >> 5;
    const int m    = blockIdx.x * 2 + w;

    float* q  = &sm[w][0];
    float* k  = q + 16 * QK_LD;
    float* sc = k + 16 * QK_LD;
    uint32_t* v32 = (uint32_t*)(sc + 16 * 17);

    const uint4* src = (const uint4*)(Y + (size_t)m * 3072);   // 384 uint4

#pragma unroll
    for (int it = 0; it < 12; it++) {
        const int f = it * 32 + lane;              // 0..383
        uint4 raw = src[f];
        if (f < 256) {                             // Q, K -> fp32
            const int sec  = f >> 7;
            const int wi   = f & 127;
            const int row  = wi >> 3;
            const int col8 = wi & 7;
            float* dst = sec ? k : q;
            const __half2* hp = (const __half2*)&raw;
            float2 f0 = __half22float2(hp[0]);
            float2 f1 = __half22float2(hp[1]);
            float2 f2 = __half22float2(hp[2]);
            float2 f3 = __half22float2(hp[3]);
            float* d = dst + row * QK_LD + col8 * 8;
            *(float4*)(d)     = make_float4(f0.x, f0.y, f1.x, f1.y);
            *(float4*)(d + 4) = make_float4(f2.x, f2.y, f3.x, f3.y);
        } else {                                   // V stays fp16
            const int wi   = f & 127;
            const int row  = wi >> 3;
            const int col8 = wi & 7;
            *(uint4*)(v32 + row * V_LD2 + col8 * 4) = raw;
        }
    }
    __syncwarp();

    // scores[h][t] = Q[h]·K[t] / 8
#pragma unroll
    for (int p = 0; p < 8; p++) {
        const int idx = p * 32 + lane;
        const int h = idx >> 4, t = idx & 15;
        float s = 0.f;
#pragma unroll
        for (int d4 = 0; d4 < 16; d4++) {
            float4 qv = *(const float4*)(q + h * QK_LD + d4 * 4);
            float4 kv = *(const float4*)(k + t * QK_LD + d4 * 4);
            s += qv.x * kv.x + qv.y * kv.y + qv.z * kv.z + qv.w * kv.w;
        }
        sc[h * 17 + t] = s * 0.125f;
    }
    __syncwarp();

    if (lane < 16) {
        float mx = -1e30f;
#pragma unroll
        for (int t = 0; t < 16; t++) mx = fmaxf(mx, sc[lane * 17 + t]);
        float sum = 0.f;
#pragma unroll
        for (int t = 0; t < 16; t++) {
            float e = __expf(sc[lane * 17 + t] - mx);
            sum += e;
            sc[lane * 17 + t] = e;
        }
        const float inv = 1.f / sum;
#pragma unroll
        for (int t = 0; t < 16; t++) sc[lane * 17 + t] *= inv;
    }
    __syncwarp();

    // O[h][2*lane..2*lane+1] = sum_t attn[h][t] * V[t][..]
    const __half2* vh = (const __half2*)v32;
    __half* dst = O + (size_t)m * 1024;
#pragma unroll
    for (int h = 0; h < 16; h++) {
        float a0 = 0.f, a1 = 0.f;
#pragma unroll
        for (int t = 0; t < 16; t++) {
            const float s = sc[h * 17 + t];
            float2 vv = __half22float2(vh[t * V_LD2 + lane]);
            a0 += s * vv.x;
            a1 += s * vv.y;
        }
        *(__half2*)(dst + h * 64 + 2 * lane) = __floats2half2_rn(a0, a1);
    }
}

// ============================================================================
extern "C" void kernel_launch(void* const* d_in, const int* in_sizes, int n_in,
                              void* d_out, int out_size)
{
    (void)in_sizes; (void)n_in; (void)out_size;
    const float* x   = (const float*)d_in[0];
    const float* Wq  = (const float*)d_in[1];
    const float* Wk  = (const float*)d_in[2];
    const float* Wv  = (const float*)d_in[3];
    const float* Wfc = (const float*)d_in[4];
    float* out = (float*)d_out;

    __half *Yh, *Oh, *Xh, *Wh;
    cudaGetSymbolAddress((void**)&Yh, g_Yh);
    cudaGetSymbolAddress((void**)&Oh, g_Oh);
    cudaGetSymbolAddress((void**)&Xh, g_Xh);
    cudaGetSymbolAddress((void**)&Wh, g_Wh);

    cudaFuncSetAttribute(gemm_f16_nt<true>,
                         cudaFuncAttributeMaxDynamicSharedMemorySize, SMEM_TOTAL);
    cudaFuncSetAttribute(gemm_f16_nt<false>,
                         cudaFuncAttributeMaxDynamicSharedMemorySize, SMEM_TOTAL);

    // fp16 conversion
    f2h_x<<<16384, 256>>>((const float4*)x, (uint2*)Xh, 4194304);
    f2h_w<<<4096, 256>>>((const float4*)Wq, (const float4*)Wk,
                         (const float4*)Wv, (const float4*)Wfc, (uint2*)Wh);

    // GEMM1: Yh = Xh @ [Wq;Wk;Wv]^T
    gemm_f16_nt<true><<<dim3(24, 128), 256, SMEM_TOTAL>>>(Xh, Wh, Yh, 3072, 1024);
    // attention
    attn_kernel<<<8192, 64>>>(Yh, Oh);
    // GEMM2: out = Oh @ Wfc^T  (fp32 out)
    gemm_f16_nt<false><<<dim3(8, 128), 256, SMEM_TOTAL>>>(Oh, Wh + 3145728, out, 1024, 1024);
}

// round 7
// speedup vs baseline: 1.1813x; 1.0210x over previous
#include <cuda_runtime.h>
#include <cuda_fp16.h>
#include <cstdint>
#include <cstddef>

// ============================================================================
// MultiHeadAttention on GB300 — FP16 mma.sync, CTA 64x128, warp 32x32,
// 3 CTA/SM (24 warps/SM), 4-stage cp.async pipeline.
//   conv : x, W -> fp16
//   GEMM1: Yh[16384,3072] = Xh @ Wqkv^T
//   attn : per-token 16x16 head attention (fp32 QK, fp16 V in smem)
//   GEMM2: out(fp32) = Oh @ Wfc^T
// ============================================================================

#define NSTG 4
#define STAGE_B 12288          // A 4KB + B 8KB
#define CTA_M 64
#define CTA_N 128
#define SMEM_TOTAL (NSTG * STAGE_B)   // 49152

__device__ __half g_Yh[50331648];   // 16384 x 3072
__device__ __half g_Oh[16777216];   // 16384 x 1024
__device__ __half g_Xh[16777216];   // x in fp16
__device__ __half g_Wh[4194304];    // Wq|Wk|Wv|Wfc in fp16

// ---------------------------------------------------------------- helpers
__device__ __forceinline__ uint32_t smem_u32(const void* p) {
    uint32_t a;
    asm("{ .reg .u64 t; cvta.to.shared.u64 t, %1; cvt.u32.u64 %0, t; }"
        : "=r"(a) : "l"(p));
    return a;
}
__device__ __forceinline__ void cp16(uint32_t saddr, const void* gptr) {
    asm volatile("cp.async.cg.shared.global [%0], [%1], 16;\n" :: "r"(saddr), "l"(gptr));
}
__device__ __forceinline__ void cp_commit() { asm volatile("cp.async.commit_group;\n"); }
template <int N>
__device__ __forceinline__ void cp_wait() {
    asm volatile("cp.async.wait_group %0;\n" :: "n"(N));
}
__device__ __forceinline__ void ldsm4(uint32_t& r0, uint32_t& r1, uint32_t& r2,
                                      uint32_t& r3, uint32_t addr) {
    asm volatile("ldmatrix.sync.aligned.m8n8.x4.shared.b16 {%0,%1,%2,%3}, [%4];"
                 : "=r"(r0), "=r"(r1), "=r"(r2), "=r"(r3) : "r"(addr));
}
__device__ __forceinline__ void mma_f16(float c[4], const uint32_t a[4], const uint32_t b[2]) {
    asm volatile(
        "mma.sync.aligned.m16n8k16.row.col.f32.f16.f16.f32 "
        "{%0,%1,%2,%3}, {%4,%5,%6,%7}, {%8,%9}, {%0,%1,%2,%3};\n"
        : "+f"(c[0]), "+f"(c[1]), "+f"(c[2]), "+f"(c[3])
        : "r"(a[0]), "r"(a[1]), "r"(a[2]), "r"(a[3]), "r"(b[0]), "r"(b[1]));
}

// ============================================================================
// FP16 NT GEMM: C[64x128 tile] = A[M,K] @ B[N,K]^T
// 8 warps, warp tile 32x32. smem row = 64B, swizzle g' = g ^ ((row>>1)&3)
// ============================================================================
template <bool OUT_HALF>
__global__ void __launch_bounds__(256, 3)
gemm_f16_nt(const __half* __restrict__ A, const __half* __restrict__ B,
            void* __restrict__ Cout, int ldc, int K)
{
    extern __shared__ __align__(128) char smem[];
    const uint32_t sb = smem_u32(smem);

    const int tid  = threadIdx.x;
    const int lane = tid & 31;
    const int wid  = tid >> 5;
    const int warp_m = wid & 1;     // 2 warps along M (32 rows)
    const int warp_n = wid >> 1;    // 4 warps along N (32 cols)

    const int mtile = blockIdx.y, ntile = blockIdx.x;
    const __half* Ab = A + (size_t)(mtile * CTA_M) * K;
    const __half* Bb = B + (size_t)(ntile * CTA_N) * K;

    // -------- loader: 3x cp16 per thread per k-tile (A 256 + B 512 float4s)
    const __half* gsrc[3];
    uint32_t soff[3];
#pragma unroll
    for (int i = 0; i < 3; i++) {
        const int id = tid + i * 256;       // 0..767
        if (id < 256) {                     // A: 64 rows
            const int rr = id >> 2, g = id & 3;
            gsrc[i] = Ab + (size_t)rr * K + g * 8;
            soff[i] = (uint32_t)(rr * 64 + ((g ^ ((rr >> 1) & 3)) << 4));
        } else {                            // B: 128 rows
            const int idb = id - 256;
            const int rr = idb >> 2, g = idb & 3;
            gsrc[i] = Bb + (size_t)rr * K + g * 8;
            soff[i] = (uint32_t)(4096 + rr * 64 + ((g ^ ((rr >> 1) & 3)) << 4));
        }
    }

    // -------- ldmatrix fragment base addresses (stage 0, ks=0)
    const int ch = lane >> 4;
    uint32_t a_addr[2], b_addr[2];
#pragma unroll
    for (int mt = 0; mt < 2; mt++) {
        const int r = warp_m * 32 + mt * 16 + (lane & 15);
        a_addr[mt] = sb + r * 64 + ((ch ^ ((r >> 1) & 3)) << 4);
    }
#pragma unroll
    for (int p = 0; p < 2; p++) {
        const int r = warp_n * 32 + p * 16 + (lane & 15);
        b_addr[p] = sb + 4096 + r * 64 + ((ch ^ ((r >> 1) & 3)) << 4);
    }

    float acc[2][4][4];
#pragma unroll
    for (int mt = 0; mt < 2; mt++)
#pragma unroll
        for (int nt = 0; nt < 4; nt++)
#pragma unroll
            for (int i = 0; i < 4; i++) acc[mt][nt][i] = 0.f;

    const int NKT = K >> 5;

    // prefill NSTG-1 stages
#pragma unroll
    for (int s = 0; s < NSTG - 1; s++) {
#pragma unroll
        for (int i = 0; i < 3; i++) cp16(sb + s * STAGE_B + soff[i], gsrc[i] + s * 32);
        cp_commit();
    }

    for (int kt = 0; kt < NKT; kt++) {
        cp_wait<NSTG - 2>();
        __syncthreads();

        const int nk = kt + NSTG - 1;
        if (nk < NKT) {
            const uint32_t so = (uint32_t)(nk % NSTG) * STAGE_B;
#pragma unroll
            for (int i = 0; i < 3; i++) cp16(sb + so + soff[i], gsrc[i] + nk * 32);
            cp_commit();
        } else {
            cp_commit();    // keep group count aligned with waits
        }

        const uint32_t so = (uint32_t)(kt % NSTG) * STAGE_B;

#pragma unroll
        for (int ks = 0; ks < 2; ks++) {
            const uint32_t kx = (uint32_t)ks << 5;
            uint32_t a[2][4], b[4][2];
#pragma unroll
            for (int mt = 0; mt < 2; mt++)
                ldsm4(a[mt][0], a[mt][1], a[mt][2], a[mt][3],
                      (a_addr[mt] + so) ^ kx);
#pragma unroll
            for (int p = 0; p < 2; p++) {
                uint32_t t0, t1, t2, t3;
                ldsm4(t0, t1, t2, t3, (b_addr[p] + so) ^ kx);
                b[2 * p][0] = t0; b[2 * p][1] = t2;
                b[2 * p + 1][0] = t1; b[2 * p + 1][1] = t3;
            }
#pragma unroll
            for (int mt = 0; mt < 2; mt++)
#pragma unroll
                for (int nt = 0; nt < 4; nt++)
                    mma_f16(acc[mt][nt], a[mt], b[nt]);
        }
    }

    // -------- epilogue
    const int r_in = lane >> 2;
    const int c_in = 2 * (lane & 3);
    if (OUT_HALF) {
        __half* Cb = (__half*)Cout + (size_t)(mtile * CTA_M) * ldc
                   + (size_t)ntile * CTA_N;
#pragma unroll
        for (int mt = 0; mt < 2; mt++)
#pragma unroll
            for (int nt = 0; nt < 4; nt++) {
                const int r0 = warp_m * 32 + mt * 16 + r_in;
                const int c0 = warp_n * 32 + nt * 8 + c_in;
                *(__half2*)(Cb + (size_t)r0 * ldc + c0) =
                    __floats2half2_rn(acc[mt][nt][0], acc[mt][nt][1]);
                *(__half2*)(Cb + (size_t)(r0 + 8) * ldc + c0) =
                    __floats2half2_rn(acc[mt][nt][2], acc[mt][nt][3]);
            }
    } else {
        float* Cb = (float*)Cout + (size_t)(mtile * CTA_M) * ldc
                  + (size_t)ntile * CTA_N;
#pragma unroll
        for (int mt = 0; mt < 2; mt++)
#pragma unroll
            for (int nt = 0; nt < 4; nt++) {
                const int r0 = warp_m * 32 + mt * 16 + r_in;
                const int c0 = warp_n * 32 + nt * 8 + c_in;
                *(float2*)(Cb + (size_t)r0 * ldc + c0) =
                    make_float2(acc[mt][nt][0], acc[mt][nt][1]);
                *(float2*)(Cb + (size_t)(r0 + 8) * ldc + c0) =
                    make_float2(acc[mt][nt][2], acc[mt][nt][3]);
            }
    }
}

// ============================================================================
// fp32 -> fp16 converters
// ============================================================================
__global__ void __launch_bounds__(256)
f2h_x(const float4* __restrict__ src, uint2* __restrict__ dst, int n4)
{
    int i = blockIdx.x * 256 + threadIdx.x;
    if (i < n4) {
        float4 v = src[i];
        __half2 h0 = __floats2half2_rn(v.x, v.y);
        __half2 h1 = __floats2half2_rn(v.z, v.w);
        uint2 o;
        o.x = *(uint32_t*)&h0;
        o.y = *(uint32_t*)&h1;
        dst[i] = o;
    }
}

__global__ void __launch_bounds__(256)
f2h_w(const float4* __restrict__ w0, const float4* __restrict__ w1,
      const float4* __restrict__ w2, const float4* __restrict__ w3,
      uint2* __restrict__ dst)
{
    int bx = blockIdx.x;
    int m  = bx >> 10;
    int i  = (bx & 1023) * 256 + threadIdx.x;
    const float4* src = (m == 0) ? w0 : (m == 1) ? w1 : (m == 2) ? w2 : w3;
    float4 v = src[i];
    __half2 h0 = __floats2half2_rn(v.x, v.y);
    __half2 h1 = __floats2half2_rn(v.z, v.w);
    uint2 o;
    o.x = *(uint32_t*)&h0;
    o.y = *(uint32_t*)&h1;
    dst[(size_t)m * 262144 + i] = o;
}

// ============================================================================
// Per-token head-axis attention: one warp/token, 2 tokens/block.
// Q,K staged fp32; V kept half2 in smem (conflict-free AV loads).
// ============================================================================
#define QK_LD 68
#define V_LD2 36
#define TOK_FLOATS (2 * 16 * QK_LD + 16 * 17 + 16 * V_LD2)
__global__ void __launch_bounds__(64)
attn_kernel(const __half* __restrict__ Y, __half* __restrict__ O)
{
    __shared__ __align__(16) float sm[2][TOK_FLOATS];

    const int lane = threadIdx.x & 31;
    const int w    = threadIdx.x >> 5;
    const int m    = blockIdx.x * 2 + w;

    float* q  = &sm[w][0];
    float* k  = q + 16 * QK_LD;
    float* sc = k + 16 * QK_LD;
    uint32_t* v32 = (uint32_t*)(sc + 16 * 17);

    const uint4* src = (const uint4*)(Y + (size_t)m * 3072);   // 384 uint4

#pragma unroll
    for (int it = 0; it < 12; it++) {
        const int f = it * 32 + lane;              // 0..383
        uint4 raw = src[f];
        if (f < 256) {                             // Q, K -> fp32
            const int sec  = f >> 7;
            const int wi   = f & 127;
            const int row  = wi >> 3;
            const int col8 = wi & 7;
            float* dst = sec ? k : q;
            const __half2* hp = (const __half2*)&raw;
            float2 f0 = __half22float2(hp[0]);
            float2 f1 = __half22float2(hp[1]);
            float2 f2 = __half22float2(hp[2]);
            float2 f3 = __half22float2(hp[3]);
            float* d = dst + row * QK_LD + col8 * 8;
            *(float4*)(d)     = make_float4(f0.x, f0.y, f1.x, f1.y);
            *(float4*)(d + 4) = make_float4(f2.x, f2.y, f3.x, f3.y);
        } else {                                   // V stays fp16
            const int wi   = f & 127;
            const int row  = wi >> 3;
            const int col8 = wi & 7;
            *(uint4*)(v32 + row * V_LD2 + col8 * 4) = raw;
        }
    }
    __syncwarp();

    // scores[h][t] = Q[h]·K[t] / 8
#pragma unroll
    for (int p = 0; p < 8; p++) {
        const int idx = p * 32 + lane;
        const int h = idx >> 4, t = idx & 15;
        float s = 0.f;
#pragma unroll
        for (int d4 = 0; d4 < 16; d4++) {
            float4 qv = *(const float4*)(q + h * QK_LD + d4 * 4);
            float4 kv = *(const float4*)(k + t * QK_LD + d4 * 4);
            s += qv.x * kv.x + qv.y * kv.y + qv.z * kv.z + qv.w * kv.w;
        }
        sc[h * 17 + t] = s * 0.125f;
    }
    __syncwarp();

    if (lane < 16) {
        float mx = -1e30f;
#pragma unroll
        for (int t = 0; t < 16; t++) mx = fmaxf(mx, sc[lane * 17 + t]);
        float sum = 0.f;
#pragma unroll
        for (int t = 0; t < 16; t++) {
            float e = __expf(sc[lane * 17 + t] - mx);
            sum += e;
            sc[lane * 17 + t] = e;
        }
        const float inv = 1.f / sum;
#pragma unroll
        for (int t = 0; t < 16; t++) sc[lane * 17 + t] *= inv;
    }
    __syncwarp();

    // O[h][2*lane..2*lane+1] = sum_t attn[h][t] * V[t][..]
    const __half2* vh = (const __half2*)v32;
    __half* dst = O + (size_t)m * 1024;
#pragma unroll
    for (int h = 0; h < 16; h++) {
        float a0 = 0.f, a1 = 0.f;
#pragma unroll
        for (int t = 0; t < 16; t++) {
            const float s = sc[h * 17 + t];
            float2 vv = __half22float2(vh[t * V_LD2 + lane]);
            a0 += s * vv.x;
            a1 += s * vv.y;
        }
        *(__half2*)(dst + h * 64 + 2 * lane) = __floats2half2_rn(a0, a1);
    }
}

// ============================================================================
extern "C" void kernel_launch(void* const* d_in, const int* in_sizes, int n_in,
                              void* d_out, int out_size)
{
    (void)in_sizes; (void)n_in; (void)out_size;
    const float* x   = (const float*)d_in[0];
    const float* Wq  = (const float*)d_in[1];
    const float* Wk  = (const float*)d_in[2];
    const float* Wv  = (const float*)d_in[3];
    const float* Wfc = (const float*)d_in[4];
    float* out = (float*)d_out;

    __half *Yh, *Oh, *Xh, *Wh;
    cudaGetSymbolAddress((void**)&Yh, g_Yh);
    cudaGetSymbolAddress((void**)&Oh, g_Oh);
    cudaGetSymbolAddress((void**)&Xh, g_Xh);
    cudaGetSymbolAddress((void**)&Wh, g_Wh);

    cudaFuncSetAttribute(gemm_f16_nt<true>,
                         cudaFuncAttributeMaxDynamicSharedMemorySize, SMEM_TOTAL);
    cudaFuncSetAttribute(gemm_f16_nt<false>,
                         cudaFuncAttributeMaxDynamicSharedMemorySize, SMEM_TOTAL);

    // fp16 conversion
    f2h_x<<<16384, 256>>>((const float4*)x, (uint2*)Xh, 4194304);
    f2h_w<<<4096, 256>>>((const float4*)Wq, (const float4*)Wk,
                         (const float4*)Wv, (const float4*)Wfc, (uint2*)Wh);

    // GEMM1: Yh = Xh @ [Wq;Wk;Wv]^T   (tiles: 24 x 256)
    gemm_f16_nt<true><<<dim3(24, 256), 256, SMEM_TOTAL>>>(Xh, Wh, Yh, 3072, 1024);
    // attention
    attn_kernel<<<8192, 64>>>(Yh, Oh);
    // GEMM2: out = Oh @ Wfc^T         (tiles: 8 x 256)
    gemm_f16_nt<false><<<dim3(8, 256), 256, SMEM_TOTAL>>>(Oh, Wh + 3145728, out, 1024, 1024);
}

// round 8
// speedup vs baseline: 1.2310x; 1.0421x over previous
#include <cuda_runtime.h>
#include <cuda_fp16.h>
#include <cstdint>
#include <cstddef>

// ============================================================================
// MultiHeadAttention on GB300 — FP16 mma.sync everywhere.
//   conv : x, W -> fp16 (single fused launch)
//   GEMM1: Yh[16384,3072] = Xh @ Wqkv^T   (CTA 64x128, warp 32x32, 3 CTA/SM)
//   attn : per-token 16x16 head attention on tensor cores (mma m16n8k16)
//   GEMM2: out(fp32) = Oh @ Wfc^T
// ============================================================================

#define NSTG 4
#define STAGE_B 12288          // A 4KB + B 8KB
#define CTA_M 64
#define CTA_N 128
#define SMEM_TOTAL (NSTG * STAGE_B)   // 49152

__device__ __half g_Yh[50331648];   // 16384 x 3072
__device__ __half g_Oh[16777216];   // 16384 x 1024
__device__ __half g_Xh[16777216];   // x in fp16
__device__ __half g_Wh[4194304];    // Wq|Wk|Wv|Wfc in fp16

// ---------------------------------------------------------------- helpers
__device__ __forceinline__ uint32_t smem_u32(const void* p) {
    uint32_t a;
    asm("{ .reg .u64 t; cvta.to.shared.u64 t, %1; cvt.u32.u64 %0, t; }"
        : "=r"(a) : "l"(p));
    return a;
}
__device__ __forceinline__ void cp16(uint32_t saddr, const void* gptr) {
    asm volatile("cp.async.cg.shared.global [%0], [%1], 16;\n" :: "r"(saddr), "l"(gptr));
}
__device__ __forceinline__ void cp_commit() { asm volatile("cp.async.commit_group;\n"); }
template <int N>
__device__ __forceinline__ void cp_wait() {
    asm volatile("cp.async.wait_group %0;\n" :: "n"(N));
}
__device__ __forceinline__ void ldsm4(uint32_t& r0, uint32_t& r1, uint32_t& r2,
                                      uint32_t& r3, uint32_t addr) {
    asm volatile("ldmatrix.sync.aligned.m8n8.x4.shared.b16 {%0,%1,%2,%3}, [%4];"
                 : "=r"(r0), "=r"(r1), "=r"(r2), "=r"(r3) : "r"(addr));
}
__device__ __forceinline__ void ldsm4t(uint32_t& r0, uint32_t& r1, uint32_t& r2,
                                       uint32_t& r3, uint32_t addr) {
    asm volatile("ldmatrix.sync.aligned.m8n8.x4.trans.shared.b16 {%0,%1,%2,%3}, [%4];"
                 : "=r"(r0), "=r"(r1), "=r"(r2), "=r"(r3) : "r"(addr));
}
__device__ __forceinline__ void mma_f16(float c[4], const uint32_t a[4], const uint32_t b[2]) {
    asm volatile(
        "mma.sync.aligned.m16n8k16.row.col.f32.f16.f16.f32 "
        "{%0,%1,%2,%3}, {%4,%5,%6,%7}, {%8,%9}, {%0,%1,%2,%3};\n"
        : "+f"(c[0]), "+f"(c[1]), "+f"(c[2]), "+f"(c[3])
        : "r"(a[0]), "r"(a[1]), "r"(a[2]), "r"(a[3]), "r"(b[0]), "r"(b[1]));
}

// ============================================================================
// FP16 NT GEMM: C[64x128 tile] = A[M,K] @ B[N,K]^T   (unchanged from R7 best)
// ============================================================================
template <bool OUT_HALF>
__global__ void __launch_bounds__(256, 3)
gemm_f16_nt(const __half* __restrict__ A, const __half* __restrict__ B,
            void* __restrict__ Cout, int ldc, int K)
{
    extern __shared__ __align__(128) char smem[];
    const uint32_t sb = smem_u32(smem);

    const int tid  = threadIdx.x;
    const int lane = tid & 31;
    const int wid  = tid >> 5;
    const int warp_m = wid & 1;
    const int warp_n = wid >> 1;

    const int mtile = blockIdx.y, ntile = blockIdx.x;
    const __half* Ab = A + (size_t)(mtile * CTA_M) * K;
    const __half* Bb = B + (size_t)(ntile * CTA_N) * K;

    const __half* gsrc[3];
    uint32_t soff[3];
#pragma unroll
    for (int i = 0; i < 3; i++) {
        const int id = tid + i * 256;
        if (id < 256) {
            const int rr = id >> 2, g = id & 3;
            gsrc[i] = Ab + (size_t)rr * K + g * 8;
            soff[i] = (uint32_t)(rr * 64 + ((g ^ ((rr >> 1) & 3)) << 4));
        } else {
            const int idb = id - 256;
            const int rr = idb >> 2, g = idb & 3;
            gsrc[i] = Bb + (size_t)rr * K + g * 8;
            soff[i] = (uint32_t)(4096 + rr * 64 + ((g ^ ((rr >> 1) & 3)) << 4));
        }
    }

    const int ch = lane >> 4;
    uint32_t a_addr[2], b_addr[2];
#pragma unroll
    for (int mt = 0; mt < 2; mt++) {
        const int r = warp_m * 32 + mt * 16 + (lane & 15);
        a_addr[mt] = sb + r * 64 + ((ch ^ ((r >> 1) & 3)) << 4);
    }
#pragma unroll
    for (int p = 0; p < 2; p++) {
        const int r = warp_n * 32 + p * 16 + (lane & 15);
        b_addr[p] = sb + 4096 + r * 64 + ((ch ^ ((r >> 1) & 3)) << 4);
    }

    float acc[2][4][4];
#pragma unroll
    for (int mt = 0; mt < 2; mt++)
#pragma unroll
        for (int nt = 0; nt < 4; nt++)
#pragma unroll
            for (int i = 0; i < 4; i++) acc[mt][nt][i] = 0.f;

    const int NKT = K >> 5;

#pragma unroll
    for (int s = 0; s < NSTG - 1; s++) {
#pragma unroll
        for (int i = 0; i < 3; i++) cp16(sb + s * STAGE_B + soff[i], gsrc[i] + s * 32);
        cp_commit();
    }

    for (int kt = 0; kt < NKT; kt++) {
        cp_wait<NSTG - 2>();
        __syncthreads();

        const int nk = kt + NSTG - 1;
        if (nk < NKT) {
            const uint32_t so = (uint32_t)(nk % NSTG) * STAGE_B;
#pragma unroll
            for (int i = 0; i < 3; i++) cp16(sb + so + soff[i], gsrc[i] + nk * 32);
            cp_commit();
        } else {
            cp_commit();
        }

        const uint32_t so = (uint32_t)(kt % NSTG) * STAGE_B;

#pragma unroll
        for (int ks = 0; ks < 2; ks++) {
            const uint32_t kx = (uint32_t)ks << 5;
            uint32_t a[2][4], b[4][2];
#pragma unroll
            for (int mt = 0; mt < 2; mt++)
                ldsm4(a[mt][0], a[mt][1], a[mt][2], a[mt][3],
                      (a_addr[mt] + so) ^ kx);
#pragma unroll
            for (int p = 0; p < 2; p++) {
                uint32_t t0, t1, t2, t3;
                ldsm4(t0, t1, t2, t3, (b_addr[p] + so) ^ kx);
                b[2 * p][0] = t0; b[2 * p][1] = t2;
                b[2 * p + 1][0] = t1; b[2 * p + 1][1] = t3;
            }
#pragma unroll
            for (int mt = 0; mt < 2; mt++)
#pragma unroll
                for (int nt = 0; nt < 4; nt++)
                    mma_f16(acc[mt][nt], a[mt], b[nt]);
        }
    }

    const int r_in = lane >> 2;
    const int c_in = 2 * (lane & 3);
    if (OUT_HALF) {
        __half* Cb = (__half*)Cout + (size_t)(mtile * CTA_M) * ldc
                   + (size_t)ntile * CTA_N;
#pragma unroll
        for (int mt = 0; mt < 2; mt++)
#pragma unroll
            for (int nt = 0; nt < 4; nt++) {
                const int r0 = warp_m * 32 + mt * 16 + r_in;
                const int c0 = warp_n * 32 + nt * 8 + c_in;
                *(__half2*)(Cb + (size_t)r0 * ldc + c0) =
                    __floats2half2_rn(acc[mt][nt][0], acc[mt][nt][1]);
                *(__half2*)(Cb + (size_t)(r0 + 8) * ldc + c0) =
                    __floats2half2_rn(acc[mt][nt][2], acc[mt][nt][3]);
            }
    } else {
        float* Cb = (float*)Cout + (size_t)(mtile * CTA_M) * ldc
                  + (size_t)ntile * CTA_N;
#pragma unroll
        for (int mt = 0; mt < 2; mt++)
#pragma unroll
            for (int nt = 0; nt < 4; nt++) {
                const int r0 = warp_m * 32 + mt * 16 + r_in;
                const int c0 = warp_n * 32 + nt * 8 + c_in;
                *(float2*)(Cb + (size_t)r0 * ldc + c0) =
                    make_float2(acc[mt][nt][0], acc[mt][nt][1]);
                *(float2*)(Cb + (size_t)(r0 + 8) * ldc + c0) =
                    make_float2(acc[mt][nt][2], acc[mt][nt][3]);
            }
    }
}

// ============================================================================
// fused fp32 -> fp16 converter: blocks [0,16384) = x, [16384,20480) = weights
// ============================================================================
__global__ void __launch_bounds__(256)
f2h_all(const float4* __restrict__ x,
        const float4* __restrict__ w0, const float4* __restrict__ w1,
        const float4* __restrict__ w2, const float4* __restrict__ w3,
        uint2* __restrict__ xdst, uint2* __restrict__ wdst)
{
    const int bx = blockIdx.x;
    const float4* src;
    uint2* dst;
    int i;
    if (bx < 16384) {
        i = bx * 256 + threadIdx.x;
        src = x; dst = xdst;
    } else {
        const int b = bx - 16384;                 // 0..4095
        const int mm = b >> 10;
        i = (b & 1023) * 256 + threadIdx.x;
        src = (mm == 0) ? w0 : (mm == 1) ? w1 : (mm == 2) ? w2 : w3;
        dst = wdst + (size_t)mm * 262144;
    }
    float4 v = src[i];
    __half2 h0 = __floats2half2_rn(v.x, v.y);
    __half2 h1 = __floats2half2_rn(v.z, v.w);
    uint2 o;
    o.x = *(uint32_t*)&h0;
    o.y = *(uint32_t*)&h1;
    dst[i] = o;
}

// ============================================================================
// Tensor-core per-token head attention. One warp per token, 8 tokens/block.
//   S[16,16] = Q Kt / 8  -> softmax in regs -> O[16,64] = P V
//   QKV staged in smem with 72-half padded rows (conflict-free LDSM/STS).
// ============================================================================
#define TPAD 72                    // halves per row (64 + 8 pad)
#define TOK_H (3 * 16 * TPAD)      // 3456 halves per token
#define ATTN_SMEM (8 * TOK_H * 2)  // 55296 bytes

__global__ void __launch_bounds__(256)
attn_tc(const __half* __restrict__ Y, __half* __restrict__ O)
{
    extern __shared__ __align__(16) __half smh[];

    const int lane = threadIdx.x & 31;
    const int w    = threadIdx.x >> 5;
    const int m    = blockIdx.x * 8 + w;

    __half* tok = smh + w * TOK_H;
    const uint32_t tb = smem_u32(tok);

    // ---- stage QKV (384 uint4 per token, 12 per lane)
    const uint4* src = (const uint4*)(Y + (size_t)m * 3072);
#pragma unroll
    for (int it = 0; it < 12; it++) {
        const int f   = it * 32 + lane;
        const int sec = f >> 7;          // 0=Q 1=K 2=V
        const int wi  = f & 127;
        const int row = wi >> 3;
        const int c8  = wi & 7;
        *(uint4*)(tok + sec * (16 * TPAD) + row * TPAD + c8 * 8) = src[f];
    }
    __syncwarp();

    // ldmatrix lane offset: matrix j = lane>>3 -> {row block, col block}
    const int rr = (lane & 7) + ((lane >> 3) & 1) * 8;   // row within 16
    const int cb = (lane >> 4) * 8;                      // col block 0/8
    const uint32_t loff = (uint32_t)(rr * TPAD + cb) * 2;    // bytes
    const uint32_t kbase = tb + 16 * TPAD * 2;    // K tile
    const uint32_t vbase = tb + 32 * TPAD * 2;    // V tile

    // ---- S = Q K^T   (2 n-tiles x 4 k-chunks)
    float s0[4] = {0.f, 0.f, 0.f, 0.f};
    float s1[4] = {0.f, 0.f, 0.f, 0.f};
#pragma unroll
    for (int kc = 0; kc < 4; kc++) {
        uint32_t a[4], kb[4];
        ldsm4(a[0], a[1], a[2], a[3], tb + loff + kc * 32);
        ldsm4(kb[0], kb[1], kb[2], kb[3], kbase + loff + kc * 32);
        uint32_t b0[2] = { kb[0], kb[2] };   // t 0-7
        uint32_t b1[2] = { kb[1], kb[3] };   // t 8-15
        mma_f16(s0, a, b0);
        mma_f16(s1, a, b1);
    }

    // ---- softmax over t (rows r=lane>>2 and r+8; each quad holds a row)
#pragma unroll
    for (int i = 0; i < 4; i++) { s0[i] *= 0.125f; s1[i] *= 0.125f; }

    float mA = fmaxf(fmaxf(s0[0], s0[1]), fmaxf(s1[0], s1[1]));
    float mB = fmaxf(fmaxf(s0[2], s0[3]), fmaxf(s1[2], s1[3]));
    mA = fmaxf(mA, __shfl_xor_sync(0xffffffff, mA, 1));
    mA = fmaxf(mA, __shfl_xor_sync(0xffffffff, mA, 2));
    mB = fmaxf(mB, __shfl_xor_sync(0xffffffff, mB, 1));
    mB = fmaxf(mB, __shfl_xor_sync(0xffffffff, mB, 2));

    float eA0 = __expf(s0[0] - mA), eA1 = __expf(s0[1] - mA);
    float eA2 = __expf(s1[0] - mA), eA3 = __expf(s1[1] - mA);
    float eB0 = __expf(s0[2] - mB), eB1 = __expf(s0[3] - mB);
    float eB2 = __expf(s1[2] - mB), eB3 = __expf(s1[3] - mB);

    float sA = eA0 + eA1 + eA2 + eA3;
    float sB = eB0 + eB1 + eB2 + eB3;
    sA += __shfl_xor_sync(0xffffffff, sA, 1);
    sA += __shfl_xor_sync(0xffffffff, sA, 2);
    sB += __shfl_xor_sync(0xffffffff, sB, 1);
    sB += __shfl_xor_sync(0xffffffff, sB, 2);
    const float iA = 1.f / sA, iB = 1.f / sB;

    // pack P as A-fragment (layout identity with S's C-fragment)
    uint32_t pa[4];
    __half2 h;
    h = __floats2half2_rn(eA0 * iA, eA1 * iA); pa[0] = *(uint32_t*)&h;
    h = __floats2half2_rn(eB0 * iB, eB1 * iB); pa[1] = *(uint32_t*)&h;
    h = __floats2half2_rn(eA2 * iA, eA3 * iA); pa[2] = *(uint32_t*)&h;
    h = __floats2half2_rn(eB2 * iB, eB3 * iB); pa[3] = *(uint32_t*)&h;

    // ---- O = P V   (8 n-tiles of 8 cols; V via ldmatrix.trans)
    float oc[8][4];
#pragma unroll
    for (int i = 0; i < 8; i++)
#pragma unroll
        for (int j = 0; j < 4; j++) oc[i][j] = 0.f;

#pragma unroll
    for (int dc = 0; dc < 4; dc++) {
        uint32_t vb[4];
        ldsm4t(vb[0], vb[1], vb[2], vb[3], vbase + loff + dc * 32);
        uint32_t bt0[2] = { vb[0], vb[1] };   // d block +0
        uint32_t bt1[2] = { vb[2], vb[3] };   // d block +8
        mma_f16(oc[2 * dc], pa, bt0);
        mma_f16(oc[2 * dc + 1], pa, bt1);
    }

    // ---- store O
    __half* dst = O + (size_t)m * 1024;
    const int r = lane >> 2;
    const int q2 = 2 * (lane & 3);
#pragma unroll
    for (int i = 0; i < 8; i++) {
        const int col = (i >> 1) * 16 + (i & 1) * 8 + q2;
        *(__half2*)(dst + r * 64 + col) =
            __floats2half2_rn(oc[i][0], oc[i][1]);
        *(__half2*)(dst + (r + 8) * 64 + col) =
            __floats2half2_rn(oc[i][2], oc[i][3]);
    }
}

// ============================================================================
extern "C" void kernel_launch(void* const* d_in, const int* in_sizes, int n_in,
                              void* d_out, int out_size)
{
    (void)in_sizes; (void)n_in; (void)out_size;
    const float* x   = (const float*)d_in[0];
    const float* Wq  = (const float*)d_in[1];
    const float* Wk  = (const float*)d_in[2];
    const float* Wv  = (const float*)d_in[3];
    const float* Wfc = (const float*)d_in[4];
    float* out = (float*)d_out;

    __half *Yh, *Oh, *Xh, *Wh;
    cudaGetSymbolAddress((void**)&Yh, g_Yh);
    cudaGetSymbolAddress((void**)&Oh, g_Oh);
    cudaGetSymbolAddress((void**)&Xh, g_Xh);
    cudaGetSymbolAddress((void**)&Wh, g_Wh);

    cudaFuncSetAttribute(gemm_f16_nt<true>,
                         cudaFuncAttributeMaxDynamicSharedMemorySize, SMEM_TOTAL);
    cudaFuncSetAttribute(gemm_f16_nt<false>,
                         cudaFuncAttributeMaxDynamicSharedMemorySize, SMEM_TOTAL);
    cudaFuncSetAttribute(attn_tc,
                         cudaFuncAttributeMaxDynamicSharedMemorySize, ATTN_SMEM);

    // fused fp16 conversion
    f2h_all<<<20480, 256>>>((const float4*)x,
                            (const float4*)Wq, (const float4*)Wk,
                            (const float4*)Wv, (const float4*)Wfc,
                            (uint2*)Xh, (uint2*)Wh);

    // GEMM1: Yh = Xh @ [Wq;Wk;Wv]^T   (tiles: 24 x 256)
    gemm_f16_nt<true><<<dim3(24, 256), 256, SMEM_TOTAL>>>(Xh, Wh, Yh, 3072, 1024);
    // tensor-core attention (8 tokens per block)
    attn_tc<<<2048, 256, ATTN_SMEM>>>(Yh, Oh);
    // GEMM2: out = Oh @ Wfc^T         (tiles: 8 x 256)
    gemm_f16_nt<false><<<dim3(8, 256), 256, SMEM_TOTAL>>>(Oh, Wh + 3145728, out, 1024, 1024);
}